// round 7
// baseline (speedup 1.0000x reference)
#include <cuda_runtime.h>
#include <cstdint>
#include <cstddef>

#define TT  8
#define NN  10000
#define FIN 128
#define HD  64
#define EE  160000
#define G4  (4*HD)          // 256 gate rows

// ---------------- scratch (static device globals; no allocation) -------------
__device__ float g_xw  [TT*NN*HD];        // x @ W_gcn            (20.5 MB)
__device__ float g_dinv[TT*NN];           // deg -> 1/sqrt(deg)   (0.3 MB)
__device__ float g_agg [TT*NN*HD];        // scattered GCN output (20.5 MB)
__device__ float g_gin [TT*NN*G4];        // precomputed input gates (82 MB)

// ---------------- helpers -----------------------------------------------------
__device__ __forceinline__ float fsig(float x) {
    return __fdividef(1.0f, 1.0f + __expf(-x));
}
__device__ __forceinline__ float ftanh_(float x) {
    float xc = fminf(fmaxf(x, -15.0f), 15.0f);
    float e  = __expf(2.0f * xc);
    return __fdividef(e - 1.0f, e + 1.0f);
}
__device__ __forceinline__ unsigned long long fma2(unsigned long long a,
                                                   unsigned long long b,
                                                   unsigned long long c) {
    unsigned long long d;
    asm("fma.rn.f32x2 %0, %1, %2, %3;" : "=l"(d) : "l"(a), "l"(b), "l"(c));
    return d;
}
__device__ __forceinline__ unsigned long long pack2(float lo, float hi) {
    unsigned long long p;
    asm("mov.b64 %0, {%1, %2};" : "=l"(p) : "f"(lo), "f"(hi));
    return p;
}
__device__ __forceinline__ float2 unpack2(unsigned long long p) {
    float lo, hi;
    asm("mov.b64 {%0, %1}, %2;" : "=f"(lo), "=f"(hi) : "l"(p));
    return make_float2(lo, hi);
}
__device__ __forceinline__ int clampN(int v) {
    return v < 0 ? 0 : (v >= NN ? NN - 1 : v);
}

// ---------------- GCN phase ---------------------------------------------------
// edge_index is int32 (JAX x64-disabled downcasts jnp.int64 -> int32).

// degree count: deg[t][dst] += 1 for every edge
__global__ void count_kernel(const int* __restrict__ ei) {
    int idx = blockIdx.x * 256 + threadIdx.x;
    if (idx >= TT * EE) return;
    int t = idx / EE;
    int e = idx - t * EE;
    int dst = clampN(ei[(size_t)t * 2 * EE + EE + e]);
    atomicAdd(&g_dinv[t * NN + dst], 1.0f);
}

// dinv = rsqrt(1 + deg)   (self-loop included)
__global__ void dinv_kernel() {
    int i = blockIdx.x * 256 + threadIdx.x;
    if (i >= TT * NN) return;
    g_dinv[i] = rsqrtf(1.0f + g_dinv[i]);
}

// xw = x @ W_gcn : 8 rows / block, W in smem
__global__ void xw_kernel(const float* __restrict__ x, const float* __restrict__ Wg) {
    __shared__ float Ws[FIN * HD];   // 32 KB
    __shared__ float xs[8][FIN];     // 4 KB
    int tid  = threadIdx.x;          // 512 threads
    int row0 = blockIdx.x * 8;
    for (int i = tid; i < FIN * HD; i += 512) Ws[i] = Wg[i];
    for (int i = tid; i < 8 * FIN;  i += 512)
        xs[i >> 7][i & 127] = x[(size_t)(row0 + (i >> 7)) * FIN + (i & 127)];
    __syncthreads();
    int r = tid >> 6, j = tid & 63;
    float acc = 0.0f;
#pragma unroll 16
    for (int k = 0; k < FIN; k++) acc = fmaf(xs[r][k], Ws[k * HD + j], acc);
    g_xw[(size_t)(row0 + r) * HD + j] = acc;
}

// scatter: agg[dst] += xw[src] * dinv[src]*dinv[dst], vectorized red.v4
__global__ void scatter_kernel(const int* __restrict__ ei) {
    int idx = blockIdx.x * 256 + threadIdx.x;        // T*E*16 threads
    int eg  = idx >> 4;
    int c   = idx & 15;
    int t   = eg / EE;
    int e   = eg - t * EE;
    int src = clampN(ei[(size_t)t * 2 * EE + e]);
    int dst = clampN(ei[(size_t)t * 2 * EE + EE + e]);
    float norm = g_dinv[t * NN + src] * g_dinv[t * NN + dst];
    const float4 v = *(const float4*)&g_xw[((size_t)t * NN + src) * HD + c * 4];
    float4 s = make_float4(v.x * norm, v.y * norm, v.z * norm, v.w * norm);
    float* p = &g_agg[((size_t)t * NN + dst) * HD + c * 4];
    asm volatile("red.global.add.v4.f32 [%0], {%1,%2,%3,%4};"
                 :: "l"(p), "f"(s.x), "f"(s.y), "f"(s.z), "f"(s.w) : "memory");
}

// gin = relu(agg + self_loop + b_gcn) @ W_ih^T + (b_ih + b_hh)
// 32 rows / block, each thread owns one W_ih row in registers
__global__ void gin_kernel(const float* __restrict__ Wih, const float* __restrict__ bgcn,
                           const float* __restrict__ bih, const float* __restrict__ bhh) {
    __shared__ float as[32][HD];     // 8 KB
    int tid  = threadIdx.x;          // 256 threads
    int row0 = blockIdx.x * 32;
    for (int i = tid; i < 32 * HD; i += 256) {
        int r = i >> 6, k = i & 63;
        int rg = row0 + r;
        float dv = g_dinv[rg];
        float v = g_agg[(size_t)rg * HD + k] + g_xw[(size_t)rg * HD + k] * dv * dv + bgcn[k];
        as[r][k] = fmaxf(v, 0.0f);
    }
    __syncthreads();
    int j = tid;                     // gate row 0..255
    float w[HD];
    const float4* wp = (const float4*)(Wih + (size_t)j * HD);
#pragma unroll
    for (int q = 0; q < 16; q++) {
        float4 v = __ldg(wp + q);
        w[4*q] = v.x; w[4*q+1] = v.y; w[4*q+2] = v.z; w[4*q+3] = v.w;
    }
    float bias = bih[j] + bhh[j];
#pragma unroll 4
    for (int r = 0; r < 32; r++) {
        float a_ = bias;
        const float4* av = (const float4*)&as[r][0];
#pragma unroll
        for (int q = 0; q < 16; q++) {
            float4 h4 = av[q];
            a_ = fmaf(h4.x, w[4*q],   a_);
            a_ = fmaf(h4.y, w[4*q+1], a_);
            a_ = fmaf(h4.z, w[4*q+2], a_);
            a_ = fmaf(h4.w, w[4*q+3], a_);
        }
        g_gin[(size_t)(row0 + r) * G4 + j] = a_;
    }
}

// ---------------- LSTM scan: one CTA per batch t (T=8 independent scans) ------
// 256 threads = 8 warps. Warp w owns hidden units [w*8, w*8+8).
// Lane layout: gate = lane>>3 (i,f,g,o), hl = lane&7 -> unit hh = w*8+hl.
// Each thread computes one gate dot (K=64) with its W_hh row pinned in
// registers as 32 packed f32x2 values; fma.rn.f32x2 halves fma-pipe pressure.
// h is double-buffered in local smem; one __syncthreads per step.
__global__ void __launch_bounds__(256, 1)
lstm_kernel(const float* __restrict__ Whh, float* __restrict__ out) {
    __shared__ __align__(16) float hbuf[2][HD];

    int t    = blockIdx.x;
    int tid  = threadIdx.x;      // 256
    int wix  = tid >> 5;         // warp 0..7
    int lane = tid & 31;
    int gate = lane >> 3;
    int hl   = lane & 7;
    int hh   = wix * 8 + hl;
    int rrow = gate * HD + hh;   // gate-row index in [0,256)

    // W_hh row pinned in registers, packed as f32x2 pairs
    unsigned long long w2[32];
    {
        const ulonglong2* wp = (const ulonglong2*)(Whh + (size_t)rrow * HD);
#pragma unroll
        for (int q = 0; q < 16; q++) {
            ulonglong2 v = __ldg(wp + q);
            w2[2*q]   = v.x;
            w2[2*q+1] = v.y;
        }
    }

    // h_0 = 0
    if (tid < HD) hbuf[0][tid] = 0.0f;
    __syncthreads();

    float c = 0.0f;
    const float* gp = g_gin + (size_t)t * NN * G4 + rrow;   // gin[t][n][rrow]
    float* op = out + (size_t)t * NN * HD + hh;             // out[t][n][hh]
    float gin_cur = __ldg(gp);

    for (int n = 0; n < NN; n++) {
        // prefetch next step's input-gate value (hides L2 latency behind compute)
        float gin_next = 0.0f;
        if (n + 1 < NN) gin_next = __ldg(gp + (size_t)(n + 1) * G4);

        int b = n & 1;
        // dot: two accumulators to break the FMA RAW chain
        unsigned long long a0 = pack2(gin_cur, 0.0f);
        unsigned long long a1 = pack2(0.0f, 0.0f);
        const ulonglong2* hv = (const ulonglong2*)&hbuf[b][0];
#pragma unroll
        for (int q = 0; q < 16; q++) {
            ulonglong2 hq = hv[q];
            a0 = fma2(hq.x, w2[2*q],   a0);
            a1 = fma2(hq.y, w2[2*q+1], a1);
        }
        float2 f0 = unpack2(a0);
        float2 f1 = unpack2(a1);
        float acc = (f0.x + f0.y) + (f1.x + f1.y);

        // gather i,f,g,o onto lanes 0..7
        float vf = __shfl_sync(0xffffffffu, acc, hl + 8);
        float vg = __shfl_sync(0xffffffffu, acc, hl + 16);
        float vo = __shfl_sync(0xffffffffu, acc, hl + 24);

        if (lane < 8) {
            float i_ = fsig(acc);
            float f_ = fsig(vf);
            float g_ = ftanh_(vg);
            float o_ = fsig(vo);
            c = f_ * c + i_ * g_;
            float h_ = o_ * ftanh_(c);

            op[(size_t)n * HD] = h_;     // output (fire and forget)
            hbuf[b ^ 1][hh] = h_;        // next step's h
        }
        __syncthreads();                 // all h writes visible before next dot
        gin_cur = gin_next;
    }
}

// ---------------- launch ------------------------------------------------------
extern "C" void kernel_launch(void* const* d_in, const int* in_sizes, int n_in,
                              void* d_out, int out_size) {
    const float* x    = (const float*)d_in[0];
    const int*   ei   = (const int*)d_in[1];     // int32! (JAX x64 disabled)
    const float* Wg   = (const float*)d_in[2];
    const float* bg   = (const float*)d_in[3];
    const float* Wih  = (const float*)d_in[4];
    const float* Whh  = (const float*)d_in[5];
    const float* bih  = (const float*)d_in[6];
    const float* bhh  = (const float*)d_in[7];
    float*       out  = (float*)d_out;

    void *p_dinv, *p_agg;
    cudaGetSymbolAddress(&p_dinv, g_dinv);
    cudaGetSymbolAddress(&p_agg,  g_agg);
    cudaMemsetAsync(p_dinv, 0, sizeof(float) * TT * NN, 0);
    cudaMemsetAsync(p_agg,  0, sizeof(float) * (size_t)TT * NN * HD, 0);

    count_kernel  <<<(TT * EE + 255) / 256, 256>>>(ei);
    dinv_kernel   <<<(TT * NN + 255) / 256, 256>>>();
    xw_kernel     <<<TT * NN / 8, 512>>>(x, Wg);
    scatter_kernel<<<(TT * EE * 16) / 256, 256>>>(ei);
    gin_kernel    <<<TT * NN / 32, 256>>>(Wih, bg, bih, bhh);
    lstm_kernel   <<<TT, 256>>>(Whh, out);
}

// round 9
// speedup vs baseline: 1.1098x; 1.1098x over previous
#include <cuda_runtime.h>
#include <cstdint>
#include <cstddef>

#define TT  8
#define NN  10000
#define FIN 128
#define HD  64
#define EE  160000
#define G4  (4*HD)          // 256 gate rows

// ---------------- scratch (static device globals; no allocation) -------------
__device__ float g_xw  [TT*NN*HD];        // x @ W_gcn            (20.5 MB)
__device__ float g_dinv[TT*NN];           // deg -> 1/sqrt(deg)   (0.3 MB)
__device__ float g_agg [TT*NN*HD];        // scattered GCN output (20.5 MB)
__device__ float g_gin [TT*G4*NN];        // input gates, TRANSPOSED [t][row][n]

// ---------------- helpers -----------------------------------------------------
__device__ __forceinline__ unsigned long long fma2(unsigned long long a,
                                                   unsigned long long b,
                                                   unsigned long long c) {
    unsigned long long d;
    asm("fma.rn.f32x2 %0, %1, %2, %3;" : "=l"(d) : "l"(a), "l"(b), "l"(c));
    return d;
}
__device__ __forceinline__ unsigned long long add2(unsigned long long a,
                                                   unsigned long long b) {
    unsigned long long d;
    asm("add.rn.f32x2 %0, %1, %2;" : "=l"(d) : "l"(a), "l"(b));
    return d;
}
__device__ __forceinline__ unsigned long long pack2(float lo, float hi) {
    unsigned long long p;
    asm("mov.b64 %0, {%1, %2};" : "=l"(p) : "f"(lo), "f"(hi));
    return p;
}
__device__ __forceinline__ float2 unpack2(unsigned long long p) {
    float lo, hi;
    asm("mov.b64 {%0, %1}, %2;" : "=f"(lo), "=f"(hi) : "l"(p));
    return make_float2(lo, hi);
}
__device__ __forceinline__ int clampN(int v) {
    return v < 0 ? 0 : (v >= NN ? NN - 1 : v);
}

// ---------------- GCN phase ---------------------------------------------------
// edge_index is int32 (JAX x64-disabled downcasts jnp.int64 -> int32).

__global__ void count_kernel(const int* __restrict__ ei) {
    int idx = blockIdx.x * 256 + threadIdx.x;
    if (idx >= TT * EE) return;
    int t = idx / EE;
    int e = idx - t * EE;
    int dst = clampN(ei[(size_t)t * 2 * EE + EE + e]);
    atomicAdd(&g_dinv[t * NN + dst], 1.0f);
}

__global__ void dinv_kernel() {
    int i = blockIdx.x * 256 + threadIdx.x;
    if (i >= TT * NN) return;
    g_dinv[i] = rsqrtf(1.0f + g_dinv[i]);
}

// xw = x @ W_gcn : 8 rows / block, W in smem
__global__ void xw_kernel(const float* __restrict__ x, const float* __restrict__ Wg) {
    __shared__ float Ws[FIN * HD];   // 32 KB
    __shared__ float xs[8][FIN];     // 4 KB
    int tid  = threadIdx.x;          // 512 threads
    int row0 = blockIdx.x * 8;
    for (int i = tid; i < FIN * HD; i += 512) Ws[i] = Wg[i];
    for (int i = tid; i < 8 * FIN;  i += 512)
        xs[i >> 7][i & 127] = x[(size_t)(row0 + (i >> 7)) * FIN + (i & 127)];
    __syncthreads();
    int r = tid >> 6, j = tid & 63;
    float acc = 0.0f;
#pragma unroll 16
    for (int k = 0; k < FIN; k++) acc = fmaf(xs[r][k], Ws[k * HD + j], acc);
    g_xw[(size_t)(row0 + r) * HD + j] = acc;
}

// scatter: agg[dst] += xw[src] * dinv[src]*dinv[dst], vectorized red.v4
__global__ void scatter_kernel(const int* __restrict__ ei) {
    int idx = blockIdx.x * 256 + threadIdx.x;        // T*E*16 threads
    int eg  = idx >> 4;
    int c   = idx & 15;
    int t   = eg / EE;
    int e   = eg - t * EE;
    int src = clampN(ei[(size_t)t * 2 * EE + e]);
    int dst = clampN(ei[(size_t)t * 2 * EE + EE + e]);
    float norm = g_dinv[t * NN + src] * g_dinv[t * NN + dst];
    const float4 v = *(const float4*)&g_xw[((size_t)t * NN + src) * HD + c * 4];
    float4 s = make_float4(v.x * norm, v.y * norm, v.z * norm, v.w * norm);
    float* p = &g_agg[((size_t)t * NN + dst) * HD + c * 4];
    asm volatile("red.global.add.v4.f32 [%0], {%1,%2,%3,%4};"
                 :: "l"(p), "f"(s.x), "f"(s.y), "f"(s.z), "f"(s.w) : "memory");
}

// gin = relu(agg + self_loop + b_gcn) @ W_ih^T + (b_ih + b_hh)
// 32 (t,n)-rows per block; OUTPUT IS TRANSPOSED: g_gin[t][gate_row][n].
// Compute into smem tile sg[256][33] then write n-coalesced.
__global__ void gin_kernel(const float* __restrict__ Wih, const float* __restrict__ bgcn,
                           const float* __restrict__ bih, const float* __restrict__ bhh) {
    __shared__ float as[32][HD];      // 8 KB
    __shared__ float sg[G4][33];      // 33 KB, padded (conflict-free transpose)
    int tid  = threadIdx.x;           // 256 threads
    int row0 = blockIdx.x * 32;       // global (t,n) row base
    for (int i = tid; i < 32 * HD; i += 256) {
        int r = i >> 6, k = i & 63;
        int rg = row0 + r;
        float dv = g_dinv[rg];
        float v = g_agg[(size_t)rg * HD + k] + g_xw[(size_t)rg * HD + k] * dv * dv + bgcn[k];
        as[r][k] = fmaxf(v, 0.0f);
    }
    __syncthreads();
    int j = tid;                      // gate row 0..255
    float w[HD];
    const float4* wp = (const float4*)(Wih + (size_t)j * HD);
#pragma unroll
    for (int q = 0; q < 16; q++) {
        float4 v = __ldg(wp + q);
        w[4*q] = v.x; w[4*q+1] = v.y; w[4*q+2] = v.z; w[4*q+3] = v.w;
    }
    float bias = bih[j] + bhh[j];
#pragma unroll 4
    for (int r = 0; r < 32; r++) {
        float a_ = bias;
        const float4* av = (const float4*)&as[r][0];
#pragma unroll
        for (int q = 0; q < 16; q++) {
            float4 h4 = av[q];
            a_ = fmaf(h4.x, w[4*q],   a_);
            a_ = fmaf(h4.y, w[4*q+1], a_);
            a_ = fmaf(h4.z, w[4*q+2], a_);
            a_ = fmaf(h4.w, w[4*q+3], a_);
        }
        sg[j][r] = a_;
    }
    __syncthreads();
    // transpose-write: warp handles 32 gate-rows; lane = local (t,n) row
    int wix  = tid >> 5;
    int lane = tid & 31;
    int rg   = row0 + lane;
    int tt_  = rg / NN;
    int nn_  = rg - tt_ * NN;
#pragma unroll 4
    for (int jj = 0; jj < 32; jj++) {
        int jr = wix * 32 + jj;
        g_gin[((size_t)tt_ * G4 + jr) * NN + nn_] = sg[jr][lane];
    }
}

// ---------------- LSTM scan: one CTA per batch t (T=8 independent scans) ------
// 256 threads = 8 warps. Lane layout: gate = lane>>3, hl = lane&7,
// hidden unit hh = (warp)*8+hl, gate-row rrow = gate*HD+hh.
// W_hh row in registers as f32x2; gin streamed via transposed layout (float4/4 steps).
// Activations computed pre-shfl in ALL lanes (parallel MUFU chains).
__global__ void __launch_bounds__(256, 1)
lstm_kernel(const float* __restrict__ Whh, float* __restrict__ out) {
    __shared__ __align__(16) float hbuf[2][HD];

    int t    = blockIdx.x;
    int tid  = threadIdx.x;
    int wix  = tid >> 5;
    int lane = tid & 31;
    int gate = lane >> 3;
    int hl   = lane & 7;
    int hh   = wix * 8 + hl;
    int rrow = gate * HD + hh;

    // per-lane activation constants: sigmoid: act = 1/(1+e^-x); tanh: 2/(1+e^-2x)-1
    float am = (gate == 2) ? 2.0f : 1.0f;   // exp multiplier
    float aa = (gate == 2) ? 2.0f : 1.0f;   // scale on r
    float ab = (gate == 2) ? -1.0f : 0.0f;  // offset

    // W_hh row pinned in registers, packed f32x2
    unsigned long long w2[32];
    {
        const ulonglong2* wp = (const ulonglong2*)(Whh + (size_t)rrow * HD);
#pragma unroll
        for (int q = 0; q < 16; q++) {
            ulonglong2 v = __ldg(wp + q);
            w2[2*q]   = v.x;
            w2[2*q+1] = v.y;
        }
    }

    if (tid < HD) hbuf[0][tid] = 0.0f;
    __syncthreads();

    float c = 0.0f;
    const float* gp = g_gin + ((size_t)t * G4 + rrow) * NN;  // transposed: stride 1 in n
    float* op = out + (size_t)t * NN * HD + hh;

    float4 cur = __ldg((const float4*)gp);
    float4 nxt = cur;

    for (int n0 = 0; n0 < NN; n0 += 4) {
        if (n0 + 4 < NN) nxt = __ldg((const float4*)(gp + n0 + 4));

#pragma unroll
        for (int s = 0; s < 4; s++) {
            int n = n0 + s;
            int b = s & 1;               // == n&1 since n0 % 4 == 0
            float ginv = (s == 0) ? cur.x : (s == 1) ? cur.y : (s == 2) ? cur.z : cur.w;

            // dot: 4 independent f32x2 chains, depth 8
            unsigned long long a0 = pack2(ginv, 0.0f);
            unsigned long long a1 = 0ull, a2 = 0ull, a3 = 0ull;
            const ulonglong2* hv = (const ulonglong2*)&hbuf[b][0];
#pragma unroll
            for (int q = 0; q < 8; q++) {
                ulonglong2 p0 = hv[2*q];
                ulonglong2 p1 = hv[2*q + 1];
                a0 = fma2(p0.x, w2[4*q],     a0);
                a1 = fma2(p0.y, w2[4*q + 1], a1);
                a2 = fma2(p1.x, w2[4*q + 2], a2);
                a3 = fma2(p1.y, w2[4*q + 3], a3);
            }
            float2 fs = unpack2(add2(add2(a0, a1), add2(a2, a3)));
            float acc = fs.x + fs.y;

            // activation in-lane (parallel across all 32 lanes)
            float u   = __expf(-am * acc);
            float r_  = __fdividef(1.0f, 1.0f + u);
            float act = fmaf(aa, r_, ab);   // i/f/o: sigmoid; g: tanh

            // gather activated f,g,o onto lanes 0..7 (i is local)
            float f_ = __shfl_sync(0xffffffffu, act, hl + 8);
            float g_ = __shfl_sync(0xffffffffu, act, hl + 16);
            float o_ = __shfl_sync(0xffffffffu, act, hl + 24);

            if (lane < 8) {
                c = fmaf(f_, c, act * g_);
                float e2 = __expf(-2.0f * c);
                float th = fmaf(2.0f, __fdividef(1.0f, 1.0f + e2), -1.0f); // tanh(c)
                float h_ = o_ * th;
                op[(size_t)n * HD] = h_;
                hbuf[b ^ 1][hh] = h_;
            }
            __syncthreads();
        }
        cur = nxt;
    }
}

// ---------------- launch ------------------------------------------------------
extern "C" void kernel_launch(void* const* d_in, const int* in_sizes, int n_in,
                              void* d_out, int out_size) {
    const float* x    = (const float*)d_in[0];
    const int*   ei   = (const int*)d_in[1];     // int32
    const float* Wg   = (const float*)d_in[2];
    const float* bg   = (const float*)d_in[3];
    const float* Wih  = (const float*)d_in[4];
    const float* Whh  = (const float*)d_in[5];
    const float* bih  = (const float*)d_in[6];
    const float* bhh  = (const float*)d_in[7];
    float*       out  = (float*)d_out;

    void *p_dinv, *p_agg;
    cudaGetSymbolAddress(&p_dinv, g_dinv);
    cudaGetSymbolAddress(&p_agg,  g_agg);
    cudaMemsetAsync(p_dinv, 0, sizeof(float) * TT * NN, 0);
    cudaMemsetAsync(p_agg,  0, sizeof(float) * (size_t)TT * NN * HD, 0);

    count_kernel  <<<(TT * EE + 255) / 256, 256>>>(ei);
    dinv_kernel   <<<(TT * NN + 255) / 256, 256>>>();
    xw_kernel     <<<TT * NN / 8, 512>>>(x, Wg);
    scatter_kernel<<<(TT * EE * 16) / 256, 256>>>(ei);
    gin_kernel    <<<TT * NN / 32, 256>>>(Wih, bg, bih, bhh);
    lstm_kernel   <<<TT, 256>>>(Whh, out);
}